// round 1
// baseline (speedup 1.0000x reference)
#include <cuda_runtime.h>
#include <float.h>

#define NROWS   65536
#define DIM     512
#define KCENT   256
#define BM      64
#define DK      16
#define THREADS 256

// Per-centroid squared norms, computed by a tiny pre-kernel each launch.
__device__ float g_cn2[KCENT];

// ---------------------------------------------------------------------------
// Pre-pass: ||c_k||^2 for all 256 centroids. One warp per centroid.
// ---------------------------------------------------------------------------
__global__ void cnorm_kernel(const float* __restrict__ cent) {
    int warp = (blockIdx.x * blockDim.x + threadIdx.x) >> 5;
    int lane = threadIdx.x & 31;
    if (warp >= KCENT) return;
    const float* row = cent + warp * DIM;
    float s = 0.f;
    #pragma unroll 4
    for (int d = lane; d < DIM; d += 32) {
        float v = row[d];
        s = fmaf(v, v, s);
    }
    #pragma unroll
    for (int o = 16; o; o >>= 1) s += __shfl_xor_sync(0xFFFFFFFFu, s, o);
    if (lane == 0) g_cn2[warp] = s;
}

// smaller score wins; tie -> smaller index (matches jax.lax.top_k on -d2)
__device__ __forceinline__ bool closer(float s, int i, float s2, int i2) {
    return (s < s2) || (s == s2 && i < i2);
}

// ---------------------------------------------------------------------------
// Main: 64-row tile x all 256 centroids, fp32 register-blocked, then
// per-row top-2 reduction and gather of the 2nd-nearest centroid row.
// Thread layout: tid = ty*16 + tx ; thread owns rows ty*4..ty*4+3,
// centroid columns {tx, tx+16, ..., tx+240} (stride-16 interleave ->
// conflict-free scalar LDS of B fragments).
// ---------------------------------------------------------------------------
__global__ __launch_bounds__(THREADS, 2)
void negsample_kernel(const float* __restrict__ emb,
                      const float* __restrict__ cent,
                      float* __restrict__ out) {
    __shared__ __align__(16) float As[DK][BM + 4];   // +4 pad: stride 68 (16B-aligned rows)
    __shared__ __align__(16) float Bs[DK][KCENT];
    __shared__ int sidx[BM];

    const int tid  = threadIdx.x;
    const int tx   = tid & 15;
    const int ty   = tid >> 4;
    const int row0 = blockIdx.x * BM;

    float acc[4][16];
    #pragma unroll
    for (int r = 0; r < 4; r++)
        #pragma unroll
        for (int j = 0; j < 16; j++) acc[r][j] = 0.f;

    for (int d0 = 0; d0 < DIM; d0 += DK) {
        // ---- load A tile (64 x 16) transposed into As[k][m] ----
        {
            int r = tid >> 2;              // 0..63
            int k = (tid & 3) * 4;         // 0,4,8,12
            float4 v = *(const float4*)(emb + (size_t)(row0 + r) * DIM + d0 + k);
            As[k + 0][r] = v.x;
            As[k + 1][r] = v.y;
            As[k + 2][r] = v.z;
            As[k + 3][r] = v.w;
        }
        // ---- load B tile (256 x 16) transposed into Bs[k][c] ----
        {
            const float* src = cent + (size_t)tid * DIM + d0;
            #pragma unroll
            for (int g = 0; g < 4; g++) {
                float4 v = *(const float4*)(src + g * 4);
                Bs[g * 4 + 0][tid] = v.x;
                Bs[g * 4 + 1][tid] = v.y;
                Bs[g * 4 + 2][tid] = v.z;
                Bs[g * 4 + 3][tid] = v.w;
            }
        }
        __syncthreads();

        #pragma unroll
        for (int kk = 0; kk < DK; kk++) {
            float4 av = *(const float4*)&As[kk][ty * 4];
            float a[4] = {av.x, av.y, av.z, av.w};
            float b[16];
            #pragma unroll
            for (int j = 0; j < 16; j++) b[j] = Bs[kk][tx + j * 16];
            #pragma unroll
            for (int r = 0; r < 4; r++)
                #pragma unroll
                for (int j = 0; j < 16; j++)
                    acc[r][j] = fmaf(a[r], b[j], acc[r][j]);
        }
        __syncthreads();
    }

    // ---- per-thread top-2 over its 16 columns (score = ||c||^2 - 2 e.c) ----
    float v1[4], v2[4];
    int   i1[4], i2[4];
    #pragma unroll
    for (int r = 0; r < 4; r++) {
        v1[r] = FLT_MAX; i1[r] = 0x7fffffff;
        v2[r] = FLT_MAX; i2[r] = 0x7fffffff;
    }
    #pragma unroll
    for (int j = 0; j < 16; j++) {
        int   col = tx + j * 16;
        float cn  = g_cn2[col];
        #pragma unroll
        for (int r = 0; r < 4; r++) {
            float s = fmaf(-2.0f, acc[r][j], cn);
            if (closer(s, col, v1[r], i1[r])) {
                v2[r] = v1[r]; i2[r] = i1[r];
                v1[r] = s;     i1[r] = col;
            } else if (closer(s, col, v2[r], i2[r])) {
                v2[r] = s;     i2[r] = col;
            }
        }
    }

    // ---- butterfly merge across the 16 lanes sharing the same ty ----
    // (same-ty threads are contiguous 16 lanes inside a warp)
    #pragma unroll
    for (int off = 8; off >= 1; off >>= 1) {
        #pragma unroll
        for (int r = 0; r < 4; r++) {
            float ov1 = __shfl_xor_sync(0xFFFFFFFFu, v1[r], off);
            int   oi1 = __shfl_xor_sync(0xFFFFFFFFu, i1[r], off);
            float ov2 = __shfl_xor_sync(0xFFFFFFFFu, v2[r], off);
            int   oi2 = __shfl_xor_sync(0xFFFFFFFFu, i2[r], off);
            // insert ov1 then ov2 (ov1 is the better of the pair)
            if (closer(ov1, oi1, v1[r], i1[r])) {
                v2[r] = v1[r]; i2[r] = i1[r];
                v1[r] = ov1;   i1[r] = oi1;
            } else if (closer(ov1, oi1, v2[r], i2[r])) {
                v2[r] = ov1;   i2[r] = oi1;
            }
            if (closer(ov2, oi2, v1[r], i1[r])) {
                v2[r] = v1[r]; i2[r] = i1[r];
                v1[r] = ov2;   i1[r] = oi2;
            } else if (closer(ov2, oi2, v2[r], i2[r])) {
                v2[r] = ov2;   i2[r] = oi2;
            }
        }
    }

    if (tx == 0) {
        #pragma unroll
        for (int r = 0; r < 4; r++) sidx[ty * 4 + r] = i2[r];
    }
    __syncthreads();

    // ---- gather: out[row] = centroids[sidx[row]] (float4, coalesced) ----
    // 64 rows x 128 float4 = 8192 float4 per block
    #pragma unroll 4
    for (int idx = tid; idx < BM * (DIM / 4); idx += THREADS) {
        int r = idx >> 7;          // /128
        int c = idx & 127;
        int ci = sidx[r];
        float4 v = *(const float4*)(cent + (size_t)ci * DIM + c * 4);
        *(float4*)(out + (size_t)(row0 + r) * DIM + c * 4) = v;
    }
}

extern "C" void kernel_launch(void* const* d_in, const int* in_sizes, int n_in,
                              void* d_out, int out_size) {
    const float* emb  = (const float*)d_in[0];
    const float* cent = (const float*)d_in[1];
    float*       out  = (float*)d_out;

    cnorm_kernel<<<8, 1024>>>(cent);                       // 256 warps -> 256 norms
    negsample_kernel<<<NROWS / BM, THREADS>>>(emb, cent, out);
}

// round 4
// speedup vs baseline: 2.2949x; 2.2949x over previous
#include <cuda_runtime.h>
#include <cuda_bf16.h>
#include <cstdint>
#include <float.h>

#define NROWS   65536
#define DIM     512
#define KCENT   256
#define BM      64           // rows per block
#define KC      64           // bf16 k-chunk (128B per row -> SW128)
#define NCHUNK  (DIM / KC)   // 8
#define NTILES  (NROWS / BM) // 1024
#define THREADS 256
#define TH      0.5f         // certainty margin (~10 sigma of approx error)
#define MAXC    16

// ---------------------------------------------------------------------------
// device globals (scratch; no allocs allowed)
// ---------------------------------------------------------------------------
__device__ float          g_cn2[KCENT];
__device__ __nv_bfloat16  g_cbf[KCENT * DIM];
__device__ int            g_amb_cnt;
__device__ int            g_amb_row[NROWS];
__device__ int            g_amb_n[NROWS];
__device__ int            g_amb_cand[NROWS][MAXC];

// ---------------------------------------------------------------------------
// helpers
// ---------------------------------------------------------------------------
__device__ __forceinline__ uint32_t smem_u32(const void* p) {
    uint32_t a;
    asm("{ .reg .u64 t; cvta.to.shared.u64 t, %1; cvt.u32.u64 %0, t; }"
        : "=r"(a) : "l"(p));
    return a;
}
__device__ __forceinline__ uint32_t swz(uint32_t o) { return o ^ ((o >> 3) & 0x70); }

#define LDM_X4(r, addr)                                                     \
    asm volatile("ldmatrix.sync.aligned.m8n8.x4.shared.b16 {%0,%1,%2,%3}, [%4];" \
        : "=r"((r)[0]), "=r"((r)[1]), "=r"((r)[2]), "=r"((r)[3]) : "r"(addr))
#define LDM_X2(r0, r1, addr)                                                \
    asm volatile("ldmatrix.sync.aligned.m8n8.x2.shared.b16 {%0,%1}, [%2];"  \
        : "=r"(r0), "=r"(r1) : "r"(addr))
#define MMA_BF16(d, a, b0, b1)                                              \
    asm volatile("mma.sync.aligned.m16n8k16.row.col.f32.bf16.bf16.f32 "     \
        "{%0,%1,%2,%3}, {%4,%5,%6,%7}, {%8,%9}, {%0,%1,%2,%3};"             \
        : "+f"((d)[0]), "+f"((d)[1]), "+f"((d)[2]), "+f"((d)[3])            \
        : "r"((a)[0]), "r"((a)[1]), "r"((a)[2]), "r"((a)[3]), "r"(b0), "r"(b1))

__device__ __forceinline__ bool closer(float s, int i, float s2, int i2) {
    return (s < s2) || (s == s2 && i < i2);
}
__device__ __forceinline__ void ins4(float v, int i, float s[4], int ix[4]) {
    if (closer(v, i, s[3], ix[3])) {
        s[3] = v; ix[3] = i;
        #pragma unroll
        for (int q = 3; q > 0; q--) {
            if (closer(s[q], ix[q], s[q - 1], ix[q - 1])) {
                float tv = s[q];  s[q] = s[q - 1];  s[q - 1] = tv;
                int   ti = ix[q]; ix[q] = ix[q - 1]; ix[q - 1] = ti;
            }
        }
    }
}

// ---------------------------------------------------------------------------
// prep: exact centroid norms + bf16 centroid copy + zero ambig counter
// ---------------------------------------------------------------------------
__global__ void prep_kernel(const float* __restrict__ cent) {
    __shared__ float ws[8];
    int b = blockIdx.x, t = threadIdx.x;
    if (b == 0 && t == 0) g_amb_cnt = 0;
    float v0 = cent[b * DIM + 2 * t];
    float v1 = cent[b * DIM + 2 * t + 1];
    g_cbf[b * DIM + 2 * t]     = __float2bfloat16(v0);
    g_cbf[b * DIM + 2 * t + 1] = __float2bfloat16(v1);
    float p = fmaf(v0, v0, v1 * v1);
    #pragma unroll
    for (int o = 16; o; o >>= 1) p += __shfl_xor_sync(0xFFFFFFFFu, p, o);
    if ((t & 31) == 0) ws[t >> 5] = p;
    __syncthreads();
    if (t == 0) {
        float s = 0.f;
        #pragma unroll
        for (int w = 0; w < 8; w++) s += ws[w];
        g_cn2[b] = s;
    }
}

// ---------------------------------------------------------------------------
// main: 64-row tile x 256 centroids via mma.sync (split-bf16, fp32 accum)
// warp grid 2x4: warp tile 32 rows x 64 cols
// dynamic smem: [0) A_hi 8K | [8192) A_lo 8K | [16384) B 32K  = 48K
// epilogue reuses [0,4K) candv, [4096,8K) candi
// ---------------------------------------------------------------------------
#define OFF_AHI   0
#define OFF_ALO   8192
#define OFF_B     16384
#define SMEM_BYTES 49152

__global__ __launch_bounds__(THREADS, 2)
void negsample_mma_kernel(const float* __restrict__ emb,
                          const float* __restrict__ cent,
                          float* __restrict__ out) {
    extern __shared__ __align__(128) char smem[];
    __shared__ float cns[KCENT];
    __shared__ int   sidx[BM];

    const uint32_t sb = smem_u32(smem);
    const int tid  = threadIdx.x;
    const int lane = tid & 31;
    const int wid  = tid >> 5;
    const int wr   = wid >> 2;        // 0..1 (row half)
    const int wc   = wid & 3;         // 0..3 (col quarter)
    const int row0 = blockIdx.x * BM;

    cns[tid] = g_cn2[tid];

    float acc[2][8][4];
    #pragma unroll
    for (int t = 0; t < 2; t++)
        #pragma unroll
        for (int j = 0; j < 8; j++)
            #pragma unroll
            for (int q = 0; q < 4; q++) acc[t][j][q] = 0.f;

    for (int kc = 0; kc < NCHUNK; kc++) {
        __syncthreads();   // previous chunk's ldmatrix reads done

        // ---- A chunk: 64 x 64 fp32 -> (hi, lo) bf16, swizzled ----
        const float* ebase = emb + (size_t)row0 * DIM + kc * KC;
        #pragma unroll
        for (int i = 0; i < 4; i++) {
            int idx = i * 256 + tid;
            int r = idx >> 4, c4 = idx & 15;
            float4 v = *(const float4*)(ebase + (size_t)r * DIM + c4 * 4);
            __nv_bfloat16 h0 = __float2bfloat16(v.x);
            __nv_bfloat16 h1 = __float2bfloat16(v.y);
            __nv_bfloat16 h2 = __float2bfloat16(v.z);
            __nv_bfloat16 h3 = __float2bfloat16(v.w);
            __nv_bfloat16 l0 = __float2bfloat16(v.x - __bfloat162float(h0));
            __nv_bfloat16 l1 = __float2bfloat16(v.y - __bfloat162float(h1));
            __nv_bfloat16 l2 = __float2bfloat16(v.z - __bfloat162float(h2));
            __nv_bfloat16 l3 = __float2bfloat16(v.w - __bfloat162float(h3));
            uint32_t hw0 = ((uint32_t)__bfloat16_as_ushort(h1) << 16) | __bfloat16_as_ushort(h0);
            uint32_t hw1 = ((uint32_t)__bfloat16_as_ushort(h3) << 16) | __bfloat16_as_ushort(h2);
            uint32_t lw0 = ((uint32_t)__bfloat16_as_ushort(l1) << 16) | __bfloat16_as_ushort(l0);
            uint32_t lw1 = ((uint32_t)__bfloat16_as_ushort(l3) << 16) | __bfloat16_as_ushort(l2);
            uint32_t bo = swz((uint32_t)(r * 128 + c4 * 8));
            *(uint2*)(smem + OFF_AHI + bo) = make_uint2(hw0, hw1);
            *(uint2*)(smem + OFF_ALO + bo) = make_uint2(lw0, lw1);
        }
        // ---- B chunk: 256 x 64 bf16, swizzled ----
        #pragma unroll
        for (int i = 0; i < 8; i++) {
            int idx = i * 256 + tid;
            int r = idx >> 3, g = idx & 7;
            uint4 v = *(const uint4*)(g_cbf + (size_t)r * DIM + kc * KC + g * 8);
            *(uint4*)(smem + OFF_B + swz((uint32_t)(r * 128 + g * 16))) = v;
        }
        __syncthreads();

        // ---- 4 k16 steps ----
        #pragma unroll
        for (int s = 0; s < 4; s++) {
            const int kb = s * 32;
            uint32_t ah[2][4], al[2][4];
            #pragma unroll
            for (int t = 0; t < 2; t++) {
                int m = wr * 32 + t * 16 + (lane & 15);
                uint32_t off = swz((uint32_t)(m * 128 + kb + ((lane >> 4) << 4)));
                LDM_X4(ah[t], sb + OFF_AHI + off);
                LDM_X4(al[t], sb + OFF_ALO + off);
            }
            #pragma unroll
            for (int j = 0; j < 8; j++) {
                int n = wc * 64 + j * 8 + (lane & 7);
                uint32_t off = swz((uint32_t)(n * 128 + kb + (((lane >> 3) & 1) << 4)));
                uint32_t b0, b1;
                LDM_X2(b0, b1, sb + OFF_B + off);
                #pragma unroll
                for (int t = 0; t < 2; t++) {
                    MMA_BF16(acc[t][j], ah[t], b0, b1);
                    MMA_BF16(acc[t][j], al[t], b0, b1);
                }
            }
        }
    }
    __syncthreads();   // all MMA smem reads done -> reuse smem for candidates

    // ---- per-lane scores + top-4 per row; merge across 4 lanes of a row ----
    float cnl[16];
    #pragma unroll
    for (int j = 0; j < 8; j++)
        #pragma unroll
        for (int b = 0; b < 2; b++)
            cnl[j * 2 + b] = cns[wc * 64 + j * 8 + (lane & 3) * 2 + b];

    float* candv = (float*)(smem);          // [64][4][4]
    int*   candi = (int*)(smem + 4096);     // [64][4][4]

    #pragma unroll
    for (int t = 0; t < 2; t++) {
        #pragma unroll
        for (int h = 0; h < 2; h++) {
            int row = wr * 32 + t * 16 + h * 8 + (lane >> 2);
            float s4[4]; int i4[4];
            #pragma unroll
            for (int q = 0; q < 4; q++) { s4[q] = FLT_MAX; i4[q] = 0x7fffffff; }
            #pragma unroll
            for (int j = 0; j < 8; j++) {
                #pragma unroll
                for (int b = 0; b < 2; b++) {
                    int   col = wc * 64 + j * 8 + (lane & 3) * 2 + b;
                    float sc  = fmaf(-2.0f, acc[t][j][h * 2 + b], cnl[j * 2 + b]);
                    ins4(sc, col, s4, i4);
                }
            }
            // butterfly merge: SNAPSHOT partner's 4 entries BEFORE inserting
            // (interleaving shfl with insertion reads partner mid-mutation -> R3 bug)
            #pragma unroll
            for (int off = 1; off <= 2; off <<= 1) {
                float ov[4]; int oi[4];
                #pragma unroll
                for (int q = 0; q < 4; q++) {
                    ov[q] = __shfl_xor_sync(0xFFFFFFFFu, s4[q], off);
                    oi[q] = __shfl_xor_sync(0xFFFFFFFFu, i4[q], off);
                }
                #pragma unroll
                for (int q = 0; q < 4; q++) ins4(ov[q], oi[q], s4, i4);
            }
            if ((lane & 3) == 0) {
                int base = (row * 4 + wc) * 4;
                #pragma unroll
                for (int q = 0; q < 4; q++) { candv[base + q] = s4[q]; candi[base + q] = i4[q]; }
            }
        }
    }
    __syncthreads();

    // ---- final per-row merge of 16 candidates; certainty test ----
    if (tid < BM) {
        int row = tid;
        float s4[4]; int i4[4];
        #pragma unroll
        for (int q = 0; q < 4; q++) { s4[q] = FLT_MAX; i4[q] = 0x7fffffff; }
        #pragma unroll
        for (int w = 0; w < 4; w++)
            #pragma unroll
            for (int q = 0; q < 4; q++)
                ins4(candv[(row * 4 + w) * 4 + q], candi[(row * 4 + w) * 4 + q], s4, i4);

        sidx[row] = i4[1];
        bool amb = (s4[1] - s4[0] <= TH) || (s4[2] - s4[1] <= TH);
        if (amb) {
            int pos = atomicAdd(&g_amb_cnt, 1);
            g_amb_row[pos] = row0 + row;
            float lim = s4[1] + TH;
            int nc = 0;
            for (int w = 0; w < 4; w++)
                for (int q = 0; q < 4; q++) {
                    float v = candv[(row * 4 + w) * 4 + q];
                    if (v <= lim && nc < MAXC)
                        g_amb_cand[pos][nc++] = candi[(row * 4 + w) * 4 + q];
                }
            g_amb_n[pos] = nc;
        }
    }
    __syncthreads();

    // ---- gather: out[row] = centroids[sidx[row]] ----
    #pragma unroll 4
    for (int idx = tid; idx < BM * (DIM / 4); idx += THREADS) {
        int r = idx >> 7, c = idx & 127;
        float4 v = *(const float4*)(cent + (size_t)sidx[r] * DIM + c * 4);
        *(float4*)(out + (size_t)(row0 + r) * DIM + c * 4) = v;
    }
}

// ---------------------------------------------------------------------------
// rescue: exact fp32 rescoring of ambiguous rows (one warp per row)
// ---------------------------------------------------------------------------
__global__ void rescue_kernel(const float* __restrict__ emb,
                              const float* __restrict__ cent,
                              float* __restrict__ out) {
    int gw   = (blockIdx.x * blockDim.x + threadIdx.x) >> 5;
    int lane = threadIdx.x & 31;
    int nw   = (gridDim.x * blockDim.x) >> 5;
    int cnt  = g_amb_cnt;

    for (int e = gw; e < cnt; e += nw) {
        int row = g_amb_row[e];
        int nc  = g_amb_n[e];
        const float* er = emb + (size_t)row * DIM;
        float fv[16];
        #pragma unroll
        for (int i = 0; i < 4; i++) {
            float4 v = *(const float4*)(er + (lane + i * 32) * 4);
            fv[i * 4 + 0] = v.x; fv[i * 4 + 1] = v.y;
            fv[i * 4 + 2] = v.z; fv[i * 4 + 3] = v.w;
        }
        float b1 = FLT_MAX, b2 = FLT_MAX;
        int   j1 = 0x7fffffff, j2 = 0x7fffffff;
        for (int q = 0; q < nc; q++) {
            int c = g_amb_cand[e][q];
            const float* cr = cent + (size_t)c * DIM;
            float p = 0.f;
            #pragma unroll
            for (int i = 0; i < 4; i++) {
                float4 u = *(const float4*)(cr + (lane + i * 32) * 4);
                p = fmaf(fv[i * 4 + 0], u.x, p);
                p = fmaf(fv[i * 4 + 1], u.y, p);
                p = fmaf(fv[i * 4 + 2], u.z, p);
                p = fmaf(fv[i * 4 + 3], u.w, p);
            }
            #pragma unroll
            for (int o = 16; o; o >>= 1) p += __shfl_xor_sync(0xFFFFFFFFu, p, o);
            float sc = fmaf(-2.0f, p, g_cn2[c]);
            if (closer(sc, c, b1, j1)) {
                b2 = b1; j2 = j1; b1 = sc; j1 = c;
            } else if (closer(sc, c, b2, j2)) {
                b2 = sc; j2 = c;
            }
        }
        const float* cr = cent + (size_t)j2 * DIM;
        float* orow = out + (size_t)row * DIM;
        #pragma unroll
        for (int i = 0; i < 4; i++) {
            *(float4*)(orow + (lane + i * 32) * 4) =
                *(const float4*)(cr + (lane + i * 32) * 4);
        }
    }
}

extern "C" void kernel_launch(void* const* d_in, const int* in_sizes, int n_in,
                              void* d_out, int out_size) {
    const float* emb  = (const float*)d_in[0];
    const float* cent = (const float*)d_in[1];
    float*       out  = (float*)d_out;

    cudaFuncSetAttribute(negsample_mma_kernel,
                         cudaFuncAttributeMaxDynamicSharedMemorySize, SMEM_BYTES);

    prep_kernel<<<KCENT, 256>>>(cent);
    negsample_mma_kernel<<<NTILES, THREADS, SMEM_BYTES>>>(emb, cent, out);
    rescue_kernel<<<256, 256>>>(emb, cent, out);
}

// round 6
// speedup vs baseline: 3.0398x; 1.3246x over previous
#include <cuda_runtime.h>
#include <cuda_fp16.h>
#include <cstdint>
#include <float.h>

#define NROWS   65536
#define DIM     512
#define KCENT   256
#define BM      64           // rows per block
#define KC      64           // fp16 k-chunk (128B per row -> SW128)
#define NCHUNK  (DIM / KC)   // 8
#define NTILES  (NROWS / BM) // 1024
#define THREADS 256
#define TH      0.5f         // certainty margin (~13 sigma of fp16 approx error)
#define MAXC    16

// ---------------------------------------------------------------------------
// device globals (scratch; no allocs allowed)
// ---------------------------------------------------------------------------
__device__ float   g_cn2[KCENT];
__device__ __half  g_chf[KCENT * DIM];
__device__ int     g_amb_cnt;
__device__ int     g_amb_row[NROWS];
__device__ int     g_amb_n[NROWS];
__device__ int     g_amb_cand[NROWS][MAXC];

// ---------------------------------------------------------------------------
// helpers
// ---------------------------------------------------------------------------
__device__ __forceinline__ uint32_t smem_u32(const void* p) {
    uint32_t a;
    asm("{ .reg .u64 t; cvta.to.shared.u64 t, %1; cvt.u32.u64 %0, t; }"
        : "=r"(a) : "l"(p));
    return a;
}
__device__ __forceinline__ uint32_t swz(uint32_t o) { return o ^ ((o >> 3) & 0x70); }

#define LDM_X4(r, addr)                                                     \
    asm volatile("ldmatrix.sync.aligned.m8n8.x4.shared.b16 {%0,%1,%2,%3}, [%4];" \
        : "=r"((r)[0]), "=r"((r)[1]), "=r"((r)[2]), "=r"((r)[3]) : "r"(addr))
#define LDM_X2(r0, r1, addr)                                                \
    asm volatile("ldmatrix.sync.aligned.m8n8.x2.shared.b16 {%0,%1}, [%2];"  \
        : "=r"(r0), "=r"(r1) : "r"(addr))
#define MMA_F16(d, a, b0, b1)                                               \
    asm volatile("mma.sync.aligned.m16n8k16.row.col.f32.f16.f16.f32 "       \
        "{%0,%1,%2,%3}, {%4,%5,%6,%7}, {%8,%9}, {%0,%1,%2,%3};"             \
        : "+f"((d)[0]), "+f"((d)[1]), "+f"((d)[2]), "+f"((d)[3])            \
        : "r"((a)[0]), "r"((a)[1]), "r"((a)[2]), "r"((a)[3]), "r"(b0), "r"(b1))
#define CP_ASYNC16(dst, src)                                                \
    asm volatile("cp.async.cg.shared.global [%0], [%1], 16;" :: "r"(dst), "l"(src))
#define CP_COMMIT() asm volatile("cp.async.commit_group;" ::: "memory")
#define CP_WAIT0()  asm volatile("cp.async.wait_group 0;" ::: "memory")

__device__ __forceinline__ bool closer(float s, int i, float s2, int i2) {
    return (s < s2) || (s == s2 && i < i2);
}
__device__ __forceinline__ void ins4(float v, int i, float s[4], int ix[4]) {
    if (closer(v, i, s[3], ix[3])) {
        s[3] = v; ix[3] = i;
        #pragma unroll
        for (int q = 3; q > 0; q--) {
            if (closer(s[q], ix[q], s[q - 1], ix[q - 1])) {
                float tv = s[q];  s[q] = s[q - 1];  s[q - 1] = tv;
                int   ti = ix[q]; ix[q] = ix[q - 1]; ix[q - 1] = ti;
            }
        }
    }
}

// ---------------------------------------------------------------------------
// prep: exact centroid norms + fp16 centroid copy + zero ambig counter
// ---------------------------------------------------------------------------
__global__ void prep_kernel(const float* __restrict__ cent) {
    __shared__ float ws[8];
    int b = blockIdx.x, t = threadIdx.x;
    if (b == 0 && t == 0) g_amb_cnt = 0;
    float v0 = cent[b * DIM + 2 * t];
    float v1 = cent[b * DIM + 2 * t + 1];
    g_chf[b * DIM + 2 * t]     = __float2half_rn(v0);
    g_chf[b * DIM + 2 * t + 1] = __float2half_rn(v1);
    float p = fmaf(v0, v0, v1 * v1);
    #pragma unroll
    for (int o = 16; o; o >>= 1) p += __shfl_xor_sync(0xFFFFFFFFu, p, o);
    if ((t & 31) == 0) ws[t >> 5] = p;
    __syncthreads();
    if (t == 0) {
        float s = 0.f;
        #pragma unroll
        for (int w = 0; w < 8; w++) s += ws[w];
        g_cn2[b] = s;
    }
}

// ---------------------------------------------------------------------------
// main: 64-row tile x 256 centroids via fp16 mma.sync, fp32 accum.
// Double-buffered smem: A 8K x2, B 32K x2 = 80K. One sync per chunk.
// warp grid 2x4: warp tile 32 rows x 64 cols.
// ---------------------------------------------------------------------------
#define OFF_A0    0
#define OFF_A1    8192
#define OFF_B0    16384
#define OFF_B1    49152
#define SMEM_BYTES 81920

__global__ __launch_bounds__(THREADS, 2)
void negsample_mma_kernel(const float* __restrict__ emb,
                          const float* __restrict__ cent,
                          float* __restrict__ out) {
    extern __shared__ __align__(128) char smem[];
    __shared__ float cns[KCENT];
    __shared__ int   sidx[BM];

    const uint32_t sb = smem_u32(smem);
    const int tid  = threadIdx.x;
    const int lane = tid & 31;
    const int wid  = tid >> 5;
    const int wr   = wid >> 2;        // 0..1 (row half)
    const int wc   = wid & 3;         // 0..3 (col quarter)
    const int row0 = blockIdx.x * BM;

    cns[tid] = g_cn2[tid];

    const uint32_t offA[2] = {OFF_A0, OFF_A1};
    const uint32_t offB[2] = {OFF_B0, OFF_B1};

    // A-load thread mapping: idx = i*256+tid -> (r = idx>>4, c4 = idx&15)
    const int ar = tid >> 4;          // base row (i adds 16 rows per step)
    const int ac4 = tid & 15;
    // B-load thread mapping: idx = i*256+tid -> (r = idx>>3, g = idx&7)
    const int br = tid >> 3;          // base row (i adds 32 rows per step)
    const int bg = tid & 7;

    float acc[2][8][4];
    #pragma unroll
    for (int t = 0; t < 2; t++)
        #pragma unroll
        for (int j = 0; j < 8; j++)
            #pragma unroll
            for (int q = 0; q < 4; q++) acc[t][j][q] = 0.f;

    // ---- prologue: A regs chunk 0, cp.async B chunk 0 -> buf 0 ----
    float4 areg[4];
    {
        const float* ebase = emb + (size_t)row0 * DIM;
        #pragma unroll
        for (int i = 0; i < 4; i++)
            areg[i] = *(const float4*)(ebase + (size_t)(ar + i * 16) * DIM + ac4 * 4);
        #pragma unroll
        for (int i = 0; i < 8; i++) {
            int r = br + i * 32;
            CP_ASYNC16(sb + OFF_B0 + swz((uint32_t)(r * 128 + bg * 16)),
                       g_chf + (size_t)r * DIM + bg * 8);
        }
        CP_COMMIT();
    }

    for (int kc = 0; kc < NCHUNK; kc++) {
        const int cur = kc & 1;

        // ---- convert prefetched A regs -> fp16 smem (swizzled) ----
        #pragma unroll
        for (int i = 0; i < 4; i++) {
            __half2 h0 = __floats2half2_rn(areg[i].x, areg[i].y);
            __half2 h1 = __floats2half2_rn(areg[i].z, areg[i].w);
            uint32_t bo = swz((uint32_t)((ar + i * 16) * 128 + ac4 * 8));
            *(uint2*)(smem + offA[cur] + bo) =
                make_uint2(*(uint32_t*)&h0, *(uint32_t*)&h1);
        }
        CP_WAIT0();
        __syncthreads();

        // ---- prefetch next chunk (overlaps MMA) ----
        if (kc + 1 < NCHUNK) {
            const float* ebase = emb + (size_t)row0 * DIM + (kc + 1) * KC;
            #pragma unroll
            for (int i = 0; i < 4; i++)
                areg[i] = *(const float4*)(ebase + (size_t)(ar + i * 16) * DIM + ac4 * 4);
            #pragma unroll
            for (int i = 0; i < 8; i++) {
                int r = br + i * 32;
                CP_ASYNC16(sb + offB[1 - cur] + swz((uint32_t)(r * 128 + bg * 16)),
                           g_chf + (size_t)r * DIM + (kc + 1) * KC + bg * 8);
            }
            CP_COMMIT();
        }

        // ---- 4 k16 MMA steps on current buffers ----
        #pragma unroll
        for (int s = 0; s < 4; s++) {
            const int kb = s * 32;
            uint32_t a[2][4];
            #pragma unroll
            for (int t = 0; t < 2; t++) {
                int m = wr * 32 + t * 16 + (lane & 15);
                uint32_t off = swz((uint32_t)(m * 128 + kb + ((lane >> 4) << 4)));
                LDM_X4(a[t], sb + offA[cur] + off);
            }
            #pragma unroll
            for (int j = 0; j < 8; j++) {
                int n = wc * 64 + j * 8 + (lane & 7);
                uint32_t off = swz((uint32_t)(n * 128 + kb + (((lane >> 3) & 1) << 4)));
                uint32_t b0, b1;
                LDM_X2(b0, b1, sb + offB[cur] + off);
                MMA_F16(acc[0][j], a[0], b0, b1);
                MMA_F16(acc[1][j], a[1], b0, b1);
            }
        }
        __syncthreads();   // MMA reads done before buffer reuse two iters ahead
    }

    // ---- per-lane scores + top-4 per row; merge across 4 lanes of a row ----
    float cnl[16];
    #pragma unroll
    for (int j = 0; j < 8; j++)
        #pragma unroll
        for (int b = 0; b < 2; b++)
            cnl[j * 2 + b] = cns[wc * 64 + j * 8 + (lane & 3) * 2 + b];

    float* candv = (float*)(smem);          // [64][4][4]
    int*   candi = (int*)(smem + 4096);     // [64][4][4]

    #pragma unroll
    for (int t = 0; t < 2; t++) {
        #pragma unroll
        for (int h = 0; h < 2; h++) {
            int row = wr * 32 + t * 16 + h * 8 + (lane >> 2);
            float s4[4]; int i4[4];
            #pragma unroll
            for (int q = 0; q < 4; q++) { s4[q] = FLT_MAX; i4[q] = 0x7fffffff; }
            #pragma unroll
            for (int j = 0; j < 8; j++) {
                #pragma unroll
                for (int b = 0; b < 2; b++) {
                    int   col = wc * 64 + j * 8 + (lane & 3) * 2 + b;
                    float sc  = fmaf(-2.0f, acc[t][j][h * 2 + b], cnl[j * 2 + b]);
                    ins4(sc, col, s4, i4);
                }
            }
            // butterfly merge: snapshot partner's entries BEFORE inserting
            #pragma unroll
            for (int off = 1; off <= 2; off <<= 1) {
                float ov[4]; int oi[4];
                #pragma unroll
                for (int q = 0; q < 4; q++) {
                    ov[q] = __shfl_xor_sync(0xFFFFFFFFu, s4[q], off);
                    oi[q] = __shfl_xor_sync(0xFFFFFFFFu, i4[q], off);
                }
                #pragma unroll
                for (int q = 0; q < 4; q++) ins4(ov[q], oi[q], s4, i4);
            }
            if ((lane & 3) == 0) {
                int base = (row * 4 + wc) * 4;
                #pragma unroll
                for (int q = 0; q < 4; q++) { candv[base + q] = s4[q]; candi[base + q] = i4[q]; }
            }
        }
    }
    __syncthreads();

    // ---- final per-row merge of 16 candidates; certainty test ----
    if (tid < BM) {
        int row = tid;
        float s4[4]; int i4[4];
        #pragma unroll
        for (int q = 0; q < 4; q++) { s4[q] = FLT_MAX; i4[q] = 0x7fffffff; }
        #pragma unroll
        for (int w = 0; w < 4; w++)
            #pragma unroll
            for (int q = 0; q < 4; q++)
                ins4(candv[(row * 4 + w) * 4 + q], candi[(row * 4 + w) * 4 + q], s4, i4);

        sidx[row] = i4[1];
        bool amb = (s4[1] - s4[0] <= TH) || (s4[2] - s4[1] <= TH);
        if (amb) {
            int pos = atomicAdd(&g_amb_cnt, 1);
            g_amb_row[pos] = row0 + row;
            float lim = s4[1] + TH;
            int nc = 0;
            for (int w = 0; w < 4; w++)
                for (int q = 0; q < 4; q++) {
                    float v = candv[(row * 4 + w) * 4 + q];
                    if (v <= lim && nc < MAXC)
                        g_amb_cand[pos][nc++] = candi[(row * 4 + w) * 4 + q];
                }
            g_amb_n[pos] = nc;
        }
    }
    __syncthreads();

    // ---- gather: out[row] = centroids[sidx[row]] ----
    #pragma unroll 4
    for (int idx = tid; idx < BM * (DIM / 4); idx += THREADS) {
        int r = idx >> 7, c = idx & 127;
        float4 v = *(const float4*)(cent + (size_t)sidx[r] * DIM + c * 4);
        *(float4*)(out + (size_t)(row0 + r) * DIM + c * 4) = v;
    }
}

// ---------------------------------------------------------------------------
// rescue: exact fp32 rescoring of ambiguous rows (one warp per row)
// ---------------------------------------------------------------------------
__global__ void rescue_kernel(const float* __restrict__ emb,
                              const float* __restrict__ cent,
                              float* __restrict__ out) {
    int gw   = (blockIdx.x * blockDim.x + threadIdx.x) >> 5;
    int lane = threadIdx.x & 31;
    int nw   = (gridDim.x * blockDim.x) >> 5;
    int cnt  = g_amb_cnt;

    for (int e = gw; e < cnt; e += nw) {
        int row = g_amb_row[e];
        int nc  = g_amb_n[e];
        const float* er = emb + (size_t)row * DIM;
        float fv[16];
        #pragma unroll
        for (int i = 0; i < 4; i++) {
            float4 v = *(const float4*)(er + (lane + i * 32) * 4);
            fv[i * 4 + 0] = v.x; fv[i * 4 + 1] = v.y;
            fv[i * 4 + 2] = v.z; fv[i * 4 + 3] = v.w;
        }
        float b1 = FLT_MAX, b2 = FLT_MAX;
        int   j1 = 0x7fffffff, j2 = 0x7fffffff;
        for (int q = 0; q < nc; q++) {
            int c = g_amb_cand[e][q];
            const float* cr = cent + (size_t)c * DIM;
            float p = 0.f;
            #pragma unroll
            for (int i = 0; i < 4; i++) {
                float4 u = *(const float4*)(cr + (lane + i * 32) * 4);
                p = fmaf(fv[i * 4 + 0], u.x, p);
                p = fmaf(fv[i * 4 + 1], u.y, p);
                p = fmaf(fv[i * 4 + 2], u.z, p);
                p = fmaf(fv[i * 4 + 3], u.w, p);
            }
            #pragma unroll
            for (int o = 16; o; o >>= 1) p += __shfl_xor_sync(0xFFFFFFFFu, p, o);
            float sc = fmaf(-2.0f, p, g_cn2[c]);
            if (closer(sc, c, b1, j1)) {
                b2 = b1; j2 = j1; b1 = sc; j1 = c;
            } else if (closer(sc, c, b2, j2)) {
                b2 = sc; j2 = c;
            }
        }
        const float* cr = cent + (size_t)j2 * DIM;
        float* orow = out + (size_t)row * DIM;
        #pragma unroll
        for (int i = 0; i < 4; i++) {
            *(float4*)(orow + (lane + i * 32) * 4) =
                *(const float4*)(cr + (lane + i * 32) * 4);
        }
    }
}

extern "C" void kernel_launch(void* const* d_in, const int* in_sizes, int n_in,
                              void* d_out, int out_size) {
    const float* emb  = (const float*)d_in[0];
    const float* cent = (const float*)d_in[1];
    float*       out  = (float*)d_out;

    cudaFuncSetAttribute(negsample_mma_kernel,
                         cudaFuncAttributeMaxDynamicSharedMemorySize, SMEM_BYTES);

    prep_kernel<<<KCENT, 256>>>(cent);
    negsample_mma_kernel<<<NTILES, THREADS, SMEM_BYTES>>>(emb, cent, out);
    rescue_kernel<<<256, 256>>>(emb, cent, out);
}

// round 7
// speedup vs baseline: 3.1039x; 1.0211x over previous
#include <cuda_runtime.h>
#include <cuda_fp16.h>
#include <cstdint>
#include <float.h>

#define NROWS   65536
#define DIM     512
#define KCENT   256
#define BM      64           // rows per block
#define KC      64           // fp16 k-chunk (128B per row -> SW128)
#define NCHUNK  (DIM / KC)   // 8
#define NTILES  (NROWS / BM) // 1024
#define THREADS 256
#define TH      0.8f         // certainty margin (~13 sigma of fp16+f16acc error)
#define MAXC    16

// ---------------------------------------------------------------------------
// device globals (scratch; no allocs allowed)
// ---------------------------------------------------------------------------
__device__ float   g_cn2[KCENT];
__device__ __half  g_chf[KCENT * DIM];
__device__ int     g_amb_cnt;
__device__ int     g_amb_row[NROWS];
__device__ int     g_amb_n[NROWS];
__device__ int     g_amb_cand[NROWS][MAXC];

// ---------------------------------------------------------------------------
// helpers
// ---------------------------------------------------------------------------
__device__ __forceinline__ uint32_t smem_u32(const void* p) {
    uint32_t a;
    asm("{ .reg .u64 t; cvta.to.shared.u64 t, %1; cvt.u32.u64 %0, t; }"
        : "=r"(a) : "l"(p));
    return a;
}
__device__ __forceinline__ uint32_t swz(uint32_t o) { return o ^ ((o >> 3) & 0x70); }

#define LDM_X4(r, addr)                                                     \
    asm volatile("ldmatrix.sync.aligned.m8n8.x4.shared.b16 {%0,%1,%2,%3}, [%4];" \
        : "=r"((r)[0]), "=r"((r)[1]), "=r"((r)[2]), "=r"((r)[3]) : "r"(addr))
#define LDM_X2(r0, r1, addr)                                                \
    asm volatile("ldmatrix.sync.aligned.m8n8.x2.shared.b16 {%0,%1}, [%2];"  \
        : "=r"(r0), "=r"(r1) : "r"(addr))
// fp16 inputs, fp16 ACCUMULATE (packed f16x2 D/C regs)
#define MMA_F16ACC(d, a, b0, b1)                                            \
    asm volatile("mma.sync.aligned.m16n8k16.row.col.f16.f16.f16.f16 "       \
        "{%0,%1}, {%2,%3,%4,%5}, {%6,%7}, {%0,%1};"                         \
        : "+r"((d)[0]), "+r"((d)[1])                                        \
        : "r"((a)[0]), "r"((a)[1]), "r"((a)[2]), "r"((a)[3]), "r"(b0), "r"(b1))
#define CP_ASYNC16(dst, src)                                                \
    asm volatile("cp.async.cg.shared.global [%0], [%1], 16;" :: "r"(dst), "l"(src))
#define CP_COMMIT() asm volatile("cp.async.commit_group;" ::: "memory")
#define CP_WAIT0()  asm volatile("cp.async.wait_group 0;" ::: "memory")

__device__ __forceinline__ bool closer(float s, int i, float s2, int i2) {
    return (s < s2) || (s == s2 && i < i2);
}
__device__ __forceinline__ void ins4(float v, int i, float s[4], int ix[4]) {
    if (closer(v, i, s[3], ix[3])) {
        s[3] = v; ix[3] = i;
        #pragma unroll
        for (int q = 3; q > 0; q--) {
            if (closer(s[q], ix[q], s[q - 1], ix[q - 1])) {
                float tv = s[q];  s[q] = s[q - 1];  s[q - 1] = tv;
                int   ti = ix[q]; ix[q] = ix[q - 1]; ix[q - 1] = ti;
            }
        }
    }
}

// ---------------------------------------------------------------------------
// prep: exact centroid norms + fp16 centroid copy + zero ambig counter
// ---------------------------------------------------------------------------
__global__ void prep_kernel(const float* __restrict__ cent) {
    __shared__ float ws[8];
    int b = blockIdx.x, t = threadIdx.x;
    if (b == 0 && t == 0) g_amb_cnt = 0;
    float v0 = cent[b * DIM + 2 * t];
    float v1 = cent[b * DIM + 2 * t + 1];
    g_chf[b * DIM + 2 * t]     = __float2half_rn(v0);
    g_chf[b * DIM + 2 * t + 1] = __float2half_rn(v1);
    float p = fmaf(v0, v0, v1 * v1);
    #pragma unroll
    for (int o = 16; o; o >>= 1) p += __shfl_xor_sync(0xFFFFFFFFu, p, o);
    if ((t & 31) == 0) ws[t >> 5] = p;
    __syncthreads();
    if (t == 0) {
        float s = 0.f;
        #pragma unroll
        for (int w = 0; w < 8; w++) s += ws[w];
        g_cn2[b] = s;
    }
}

// ---------------------------------------------------------------------------
// main: 64-row tile x 256 centroids, fp16 mma.sync with f16 accumulation
// inside each 64-dim chunk, promoted to fp32 across chunks.
// Double-buffered smem: A 8K x2, B 32K x2 = 80K. One sync per chunk.
// warp grid 2x4: warp tile 32 rows x 64 cols (two 16-row t-halves).
// ---------------------------------------------------------------------------
#define OFF_A0    0
#define OFF_A1    8192
#define OFF_B0    16384
#define OFF_B1    49152
#define SMEM_BYTES 81920

__global__ __launch_bounds__(THREADS, 2)
void negsample_mma_kernel(const float* __restrict__ emb,
                          const float* __restrict__ cent,
                          float* __restrict__ out) {
    extern __shared__ __align__(128) char smem[];
    __shared__ float cns[KCENT];
    __shared__ int   sidx[BM];

    const uint32_t sb = smem_u32(smem);
    const int tid  = threadIdx.x;
    const int lane = tid & 31;
    const int wid  = tid >> 5;
    const int wr   = wid >> 2;        // 0..1 (row half)
    const int wc   = wid & 3;         // 0..3 (col quarter)
    const int row0 = blockIdx.x * BM;

    cns[tid] = g_cn2[tid];

    const uint32_t offA[2] = {OFF_A0, OFF_A1};
    const uint32_t offB[2] = {OFF_B0, OFF_B1};

    const int ar  = tid >> 4;         // A-load: base row
    const int ac4 = tid & 15;
    const int br  = tid >> 3;         // B-load: base row
    const int bg  = tid & 7;

    float acc[2][8][4];
    #pragma unroll
    for (int t = 0; t < 2; t++)
        #pragma unroll
        for (int j = 0; j < 8; j++)
            #pragma unroll
            for (int q = 0; q < 4; q++) acc[t][j][q] = 0.f;

    // ---- prologue: A regs chunk 0, cp.async B chunk 0 -> buf 0 ----
    float4 areg[4];
    {
        const float* ebase = emb + (size_t)row0 * DIM;
        #pragma unroll
        for (int i = 0; i < 4; i++)
            areg[i] = *(const float4*)(ebase + (size_t)(ar + i * 16) * DIM + ac4 * 4);
        #pragma unroll
        for (int i = 0; i < 8; i++) {
            int r = br + i * 32;
            CP_ASYNC16(sb + OFF_B0 + swz((uint32_t)(r * 128 + bg * 16)),
                       g_chf + (size_t)r * DIM + bg * 8);
        }
        CP_COMMIT();
    }

    for (int kc = 0; kc < NCHUNK; kc++) {
        const int cur = kc & 1;

        // ---- convert prefetched A regs -> fp16 smem (swizzled) ----
        #pragma unroll
        for (int i = 0; i < 4; i++) {
            __half2 h0 = __floats2half2_rn(areg[i].x, areg[i].y);
            __half2 h1 = __floats2half2_rn(areg[i].z, areg[i].w);
            uint32_t bo = swz((uint32_t)((ar + i * 16) * 128 + ac4 * 8));
            *(uint2*)(smem + offA[cur] + bo) =
                make_uint2(*(uint32_t*)&h0, *(uint32_t*)&h1);
        }
        CP_WAIT0();
        __syncthreads();

        // ---- prefetch next chunk (overlaps MMA) ----
        if (kc + 1 < NCHUNK) {
            const float* ebase = emb + (size_t)row0 * DIM + (kc + 1) * KC;
            #pragma unroll
            for (int i = 0; i < 4; i++)
                areg[i] = *(const float4*)(ebase + (size_t)(ar + i * 16) * DIM + ac4 * 4);
            #pragma unroll
            for (int i = 0; i < 8; i++) {
                int r = br + i * 32;
                CP_ASYNC16(sb + offB[1 - cur] + swz((uint32_t)(r * 128 + bg * 16)),
                           g_chf + (size_t)r * DIM + (kc + 1) * KC + bg * 8);
            }
            CP_COMMIT();
        }

        // ---- two t-halves; f16 accumulate inside the chunk, then promote ----
        #pragma unroll
        for (int t = 0; t < 2; t++) {
            uint32_t cf[8][2];
            #pragma unroll
            for (int j = 0; j < 8; j++) { cf[j][0] = 0u; cf[j][1] = 0u; }

            #pragma unroll
            for (int s = 0; s < 4; s++) {
                const int kb = s * 32;
                uint32_t a[4];
                int m = wr * 32 + t * 16 + (lane & 15);
                LDM_X4(a, sb + offA[cur] +
                       swz((uint32_t)(m * 128 + kb + ((lane >> 4) << 4))));
                #pragma unroll
                for (int j = 0; j < 8; j++) {
                    int n = wc * 64 + j * 8 + (lane & 7);
                    uint32_t b0, b1;
                    LDM_X2(b0, b1, sb + offB[cur] +
                           swz((uint32_t)(n * 128 + kb + (((lane >> 3) & 1) << 4))));
                    MMA_F16ACC(cf[j], a, b0, b1);
                }
            }
            // promote chunk partials to fp32
            #pragma unroll
            for (int j = 0; j < 8; j++) {
                float2 f0 = __half22float2(*(__half2*)&cf[j][0]);
                float2 f1 = __half22float2(*(__half2*)&cf[j][1]);
                acc[t][j][0] += f0.x; acc[t][j][1] += f0.y;
                acc[t][j][2] += f1.x; acc[t][j][3] += f1.y;
            }
        }
        // no trailing sync needed: next iter writes only the opposite buffer;
        // the mid-sync of iter kc+1 orders iter-kc MMA reads vs iter-kc+2 writes
    }
    __syncthreads();   // all MMA smem reads done -> reuse smem for candidates

    // ---- per-lane scores + top-4 per row; merge across 4 lanes of a row ----
    float cnl[16];
    #pragma unroll
    for (int j = 0; j < 8; j++)
        #pragma unroll
        for (int b = 0; b < 2; b++)
            cnl[j * 2 + b] = cns[wc * 64 + j * 8 + (lane & 3) * 2 + b];

    float* candv = (float*)(smem);          // [64][4][4]
    int*   candi = (int*)(smem + 4096);     // [64][4][4]

    #pragma unroll
    for (int t = 0; t < 2; t++) {
        #pragma unroll
        for (int h = 0; h < 2; h++) {
            int row = wr * 32 + t * 16 + h * 8 + (lane >> 2);
            float s4[4]; int i4[4];
            #pragma unroll
            for (int q = 0; q < 4; q++) { s4[q] = FLT_MAX; i4[q] = 0x7fffffff; }
            #pragma unroll
            for (int j = 0; j < 8; j++) {
                #pragma unroll
                for (int b = 0; b < 2; b++) {
                    int   col = wc * 64 + j * 8 + (lane & 3) * 2 + b;
                    float sc  = fmaf(-2.0f, acc[t][j][h * 2 + b], cnl[j * 2 + b]);
                    ins4(sc, col, s4, i4);
                }
            }
            // butterfly merge: snapshot partner's entries BEFORE inserting
            #pragma unroll
            for (int off = 1; off <= 2; off <<= 1) {
                float ov[4]; int oi[4];
                #pragma unroll
                for (int q = 0; q < 4; q++) {
                    ov[q] = __shfl_xor_sync(0xFFFFFFFFu, s4[q], off);
                    oi[q] = __shfl_xor_sync(0xFFFFFFFFu, i4[q], off);
                }
                #pragma unroll
                for (int q = 0; q < 4; q++) ins4(ov[q], oi[q], s4, i4);
            }
            if ((lane & 3) == 0) {
                int base = (row * 4 + wc) * 4;
                #pragma unroll
                for (int q = 0; q < 4; q++) { candv[base + q] = s4[q]; candi[base + q] = i4[q]; }
            }
        }
    }
    __syncthreads();

    // ---- final per-row merge of 16 candidates; certainty test ----
    if (tid < BM) {
        int row = tid;
        float s4[4]; int i4[4];
        #pragma unroll
        for (int q = 0; q < 4; q++) { s4[q] = FLT_MAX; i4[q] = 0x7fffffff; }
        #pragma unroll
        for (int w = 0; w < 4; w++)
            #pragma unroll
            for (int q = 0; q < 4; q++)
                ins4(candv[(row * 4 + w) * 4 + q], candi[(row * 4 + w) * 4 + q], s4, i4);

        sidx[row] = i4[1];
        bool amb = (s4[1] - s4[0] <= TH) || (s4[2] - s4[1] <= TH);
        if (amb) {
            int pos = atomicAdd(&g_amb_cnt, 1);
            g_amb_row[pos] = row0 + row;
            float lim = s4[1] + TH;
            int nc = 0;
            for (int w = 0; w < 4; w++)
                for (int q = 0; q < 4; q++) {
                    float v = candv[(row * 4 + w) * 4 + q];
                    if (v <= lim && nc < MAXC)
                        g_amb_cand[pos][nc++] = candi[(row * 4 + w) * 4 + q];
                }
            g_amb_n[pos] = nc;
        }
    }
    __syncthreads();

    // ---- gather: out[row] = centroids[sidx[row]] ----
    #pragma unroll 4
    for (int idx = tid; idx < BM * (DIM / 4); idx += THREADS) {
        int r = idx >> 7, c = idx & 127;
        float4 v = *(const float4*)(cent + (size_t)sidx[r] * DIM + c * 4);
        *(float4*)(out + (size_t)(row0 + r) * DIM + c * 4) = v;
    }
}

// ---------------------------------------------------------------------------
// rescue: exact fp32 rescoring of ambiguous rows (one warp per row)
// ---------------------------------------------------------------------------
__global__ void rescue_kernel(const float* __restrict__ emb,
                              const float* __restrict__ cent,
                              float* __restrict__ out) {
    int gw   = (blockIdx.x * blockDim.x + threadIdx.x) >> 5;
    int lane = threadIdx.x & 31;
    int nw   = (gridDim.x * blockDim.x) >> 5;
    int cnt  = g_amb_cnt;

    for (int e = gw; e < cnt; e += nw) {
        int row = g_amb_row[e];
        int nc  = g_amb_n[e];
        const float* er = emb + (size_t)row * DIM;
        float fv[16];
        #pragma unroll
        for (int i = 0; i < 4; i++) {
            float4 v = *(const float4*)(er + (lane + i * 32) * 4);
            fv[i * 4 + 0] = v.x; fv[i * 4 + 1] = v.y;
            fv[i * 4 + 2] = v.z; fv[i * 4 + 3] = v.w;
        }
        float b1 = FLT_MAX, b2 = FLT_MAX;
        int   j1 = 0x7fffffff, j2 = 0x7fffffff;
        for (int q = 0; q < nc; q++) {
            int c = g_amb_cand[e][q];
            const float* cr = cent + (size_t)c * DIM;
            float p = 0.f;
            #pragma unroll
            for (int i = 0; i < 4; i++) {
                float4 u = *(const float4*)(cr + (lane + i * 32) * 4);
                p = fmaf(fv[i * 4 + 0], u.x, p);
                p = fmaf(fv[i * 4 + 1], u.y, p);
                p = fmaf(fv[i * 4 + 2], u.z, p);
                p = fmaf(fv[i * 4 + 3], u.w, p);
            }
            #pragma unroll
            for (int o = 16; o; o >>= 1) p += __shfl_xor_sync(0xFFFFFFFFu, p, o);
            float sc = fmaf(-2.0f, p, g_cn2[c]);
            if (closer(sc, c, b1, j1)) {
                b2 = b1; j2 = j1; b1 = sc; j1 = c;
            } else if (closer(sc, c, b2, j2)) {
                b2 = sc; j2 = c;
            }
        }
        const float* cr = cent + (size_t)j2 * DIM;
        float* orow = out + (size_t)row * DIM;
        #pragma unroll
        for (int i = 0; i < 4; i++) {
            *(float4*)(orow + (lane + i * 32) * 4) =
                *(const float4*)(cr + (lane + i * 32) * 4);
        }
    }
}

extern "C" void kernel_launch(void* const* d_in, const int* in_sizes, int n_in,
                              void* d_out, int out_size) {
    const float* emb  = (const float*)d_in[0];
    const float* cent = (const float*)d_in[1];
    float*       out  = (float*)d_out;

    cudaFuncSetAttribute(negsample_mma_kernel,
                         cudaFuncAttributeMaxDynamicSharedMemorySize, SMEM_BYTES);

    prep_kernel<<<KCENT, 256>>>(cent);
    negsample_mma_kernel<<<NTILES, THREADS, SMEM_BYTES>>>(emb, cent, out);
    rescue_kernel<<<512, 256>>>(emb, cent, out);
}